// round 3
// baseline (speedup 1.0000x reference)
#include <cuda_runtime.h>

#define HIDDEN   1024
#define BATCH    2
#define SEQ      2048
#define NHEADS   16
#define HDIM     64
#define MROWS    (BATCH * SEQ)   // 4096

// ---------------------------------------------------------------------------
// Scratch (static device globals — no runtime allocation allowed)
// ---------------------------------------------------------------------------
__device__ __align__(256) float g_q[BATCH * NHEADS * SEQ * HDIM];   // 16 MB
__device__ __align__(256) float g_k[BATCH * NHEADS * SEQ * HDIM];   // 16 MB
__device__ __align__(256) float g_v[BATCH * NHEADS * SEQ * HDIM];   // 16 MB
__device__ __align__(256) float g_ao[MROWS * HIDDEN];               // 16 MB

// ---------------------------------------------------------------------------
// SGEMM: C[M,N] = A[M,K] @ B[N,K]^T + bias[N]
//   mode 0: plain write to C (used for O-projection; A==nullptr -> read g_ao)
//   mode 1: scatter epilogue into g_q/g_k/g_v head-major layout
// Tiling: BM=128, BN=128, BK=16, 256 threads, 8x8 microtile per thread.
// ---------------------------------------------------------------------------
#define BM  128
#define BN  128
#define BKK 16

__global__ __launch_bounds__(256, 2)
void sgemm_kernel(const float* __restrict__ A, const float* __restrict__ Bm,
                  const float* __restrict__ bias, float* __restrict__ C,
                  int M, int N, int K, int mode)
{
    __shared__ float As[BKK][BM + 4];
    __shared__ float Bs[BKK][BN + 4];

    const int tid = threadIdx.x;
    const int tx  = tid & 15;      // 0..15 -> N microtile
    const int ty  = tid >> 4;      // 0..15 -> M microtile
    const int bm  = blockIdx.y * BM;
    const int bn  = blockIdx.x * BN;

    const float* Aeff = A ? A : g_ao;

    // Loader mapping: each thread loads 2 float4 from A and 2 from B per k-step
    const int ar = tid >> 2;           // 0..63
    const int ac = (tid & 3) << 2;     // 0,4,8,12
    const float* ap = Aeff + (size_t)(bm + ar) * K + ac;
    const float* bp = Bm   + (size_t)(bn + ar) * K + ac;

    float acc[8][8];
#pragma unroll
    for (int i = 0; i < 8; i++)
#pragma unroll
        for (int j = 0; j < 8; j++) acc[i][j] = 0.f;

    for (int k0 = 0; k0 < K; k0 += BKK) {
        float4 a0 = *(const float4*)(ap);
        float4 a1 = *(const float4*)(ap + (size_t)64 * K);
        float4 b0 = *(const float4*)(bp);
        float4 b1 = *(const float4*)(bp + (size_t)64 * K);
        ap += BKK; bp += BKK;

        __syncthreads();   // previous compute phase done reading smem
        As[ac + 0][ar]      = a0.x; As[ac + 1][ar]      = a0.y;
        As[ac + 2][ar]      = a0.z; As[ac + 3][ar]      = a0.w;
        As[ac + 0][ar + 64] = a1.x; As[ac + 1][ar + 64] = a1.y;
        As[ac + 2][ar + 64] = a1.z; As[ac + 3][ar + 64] = a1.w;
        Bs[ac + 0][ar]      = b0.x; Bs[ac + 1][ar]      = b0.y;
        Bs[ac + 2][ar]      = b0.z; Bs[ac + 3][ar]      = b0.w;
        Bs[ac + 0][ar + 64] = b1.x; Bs[ac + 1][ar + 64] = b1.y;
        Bs[ac + 2][ar + 64] = b1.z; Bs[ac + 3][ar + 64] = b1.w;
        __syncthreads();

#pragma unroll
        for (int kk = 0; kk < BKK; kk++) {
            float ra[8], rb[8];
            *(float4*)&ra[0] = *(const float4*)&As[kk][ty * 8];
            *(float4*)&ra[4] = *(const float4*)&As[kk][ty * 8 + 4];
            *(float4*)&rb[0] = *(const float4*)&Bs[kk][tx * 8];
            *(float4*)&rb[4] = *(const float4*)&Bs[kk][tx * 8 + 4];
#pragma unroll
            for (int i = 0; i < 8; i++)
#pragma unroll
                for (int j = 0; j < 8; j++)
                    acc[i][j] = fmaf(ra[i], rb[j], acc[i][j]);
        }
    }

    float rbias[8];
#pragma unroll
    for (int j = 0; j < 8; j++) rbias[j] = bias[bn + tx * 8 + j];

    if (mode == 0) {
#pragma unroll
        for (int i = 0; i < 8; i++) {
            const int row = bm + ty * 8 + i;
            float4 v0, v1;
            v0.x = acc[i][0] + rbias[0]; v0.y = acc[i][1] + rbias[1];
            v0.z = acc[i][2] + rbias[2]; v0.w = acc[i][3] + rbias[3];
            v1.x = acc[i][4] + rbias[4]; v1.y = acc[i][5] + rbias[5];
            v1.z = acc[i][6] + rbias[6]; v1.w = acc[i][7] + rbias[7];
            *(float4*)&C[(size_t)row * N + bn + tx * 8]     = v0;
            *(float4*)&C[(size_t)row * N + bn + tx * 8 + 4] = v1;
        }
    } else {
        // Scatter into g_q/g_k/g_v as [b][h][n][hd]
#pragma unroll
        for (int i = 0; i < 8; i++) {
            const int m = bm + ty * 8 + i;
            const int b = m >> 11;          // /SEQ (2048)
            const int n = m & 2047;
#pragma unroll
            for (int jj = 0; jj < 8; jj += 4) {
                const int e    = bn + tx * 8 + jj;
                const int part = e >> 10;       // 0:q 1:k 2:v
                const int c    = e & 1023;
                const int h    = c >> 6;
                const int hd   = c & 63;        // hd .. hd+3 stay in same head
                float* dst = (part == 0) ? g_q : ((part == 1) ? g_k : g_v);
                float4 v;
                v.x = acc[i][jj + 0] + rbias[jj + 0];
                v.y = acc[i][jj + 1] + rbias[jj + 1];
                v.z = acc[i][jj + 2] + rbias[jj + 2];
                v.w = acc[i][jj + 3] + rbias[jj + 3];
                *(float4*)&dst[(((size_t)(b * NHEADS + h) * SEQ) + n) * HDIM + hd] = v;
            }
        }
    }
}

// ---------------------------------------------------------------------------
// Fused flash attention (fp32, online softmax).
// Block: 64 queries x full HDIM=64 of one (b,h). 256 threads, 4x4 microtiles.
// Smem (dynamic, 52224 B): Qt[d][q], Kt[d][k] (reused as P[q][k]), Vs[k][d],
// all stride 68 floats.
// ---------------------------------------------------------------------------
#define AST 68
#define ATTN_SMEM (3 * 64 * AST * 4)

__global__ __launch_bounds__(256)
void attn_kernel()
{
    extern __shared__ float sm[];
    float* Qt = sm;                 // [d][q]
    float* Kt = sm + 64 * AST;      // [d][k], then reused as P[q][k]
    float* Vs = sm + 2 * 64 * AST;  // [k][d]

    const int tid = threadIdx.x;
    const int tx  = tid & 15;       // key / d-column microtile
    const int ty  = tid >> 4;       // query microtile
    const int qt  = blockIdx.x;     // 0..31
    const int h   = blockIdx.y;
    const int b   = blockIdx.z;

    const size_t head_off = (size_t)(b * NHEADS + h) * SEQ * HDIM;
    const float* qp = g_q + head_off + (size_t)qt * 64 * HDIM;
    const float* kp = g_k + head_off;
    const float* vp = g_v + head_off;

    const int lr = tid >> 2;            // 0..63
    const int lc = (tid & 3) << 4;      // 0,16,32,48

    // Load Q tile transposed: Qt[d][q]
#pragma unroll
    for (int u = 0; u < 4; u++) {
        float4 v = *(const float4*)(qp + (size_t)lr * HDIM + lc + u * 4);
        Qt[(lc + u * 4 + 0) * AST + lr] = v.x;
        Qt[(lc + u * 4 + 1) * AST + lr] = v.y;
        Qt[(lc + u * 4 + 2) * AST + lr] = v.z;
        Qt[(lc + u * 4 + 3) * AST + lr] = v.w;
    }

    float acc[4][4];
    float mrow[4], lrow[4];
#pragma unroll
    for (int i = 0; i < 4; i++) {
        mrow[i] = -3.0e38f;
        lrow[i] = 0.f;
#pragma unroll
        for (int j = 0; j < 4; j++) acc[i][j] = 0.f;
    }

    for (int kt = 0; kt < SEQ / 64; kt++) {
        float4 kreg[4], vreg[4];
        const float* kr = kp + (size_t)kt * 64 * HDIM + (size_t)lr * HDIM + lc;
        const float* vr = vp + (size_t)kt * 64 * HDIM + (size_t)lr * HDIM + lc;
#pragma unroll
        for (int u = 0; u < 4; u++) {
            kreg[u] = *(const float4*)(kr + u * 4);
            vreg[u] = *(const float4*)(vr + u * 4);
        }

        __syncthreads();   // previous PV done with Kt/Vs (and Qt visible on iter 0)
#pragma unroll
        for (int u = 0; u < 4; u++) {
            Kt[(lc + u * 4 + 0) * AST + lr] = kreg[u].x;
            Kt[(lc + u * 4 + 1) * AST + lr] = kreg[u].y;
            Kt[(lc + u * 4 + 2) * AST + lr] = kreg[u].z;
            Kt[(lc + u * 4 + 3) * AST + lr] = kreg[u].w;
            *(float4*)(Vs + lr * AST + lc + u * 4) = vreg[u];
        }
        __syncthreads();

        // S = Q K^T (4x4 per thread)
        float s[4][4];
#pragma unroll
        for (int i = 0; i < 4; i++)
#pragma unroll
            for (int j = 0; j < 4; j++) s[i][j] = 0.f;

#pragma unroll 8
        for (int d = 0; d < HDIM; d++) {
            float4 q4 = *(const float4*)(Qt + d * AST + ty * 4);
            float4 k4 = *(const float4*)(Kt + d * AST + tx * 4);
            float qa[4] = {q4.x, q4.y, q4.z, q4.w};
            float ka[4] = {k4.x, k4.y, k4.z, k4.w};
#pragma unroll
            for (int i = 0; i < 4; i++)
#pragma unroll
                for (int j = 0; j < 4; j++)
                    s[i][j] = fmaf(qa[i], ka[j], s[i][j]);
        }

        // Online softmax update (rows owned by 16-lane groups sharing ty)
#pragma unroll
        for (int i = 0; i < 4; i++) {
#pragma unroll
            for (int j = 0; j < 4; j++) s[i][j] *= 0.125f;   // 1/sqrt(64)
            float rm = fmaxf(fmaxf(s[i][0], s[i][1]), fmaxf(s[i][2], s[i][3]));
#pragma unroll
            for (int off = 8; off > 0; off >>= 1)
                rm = fmaxf(rm, __shfl_xor_sync(0xffffffffu, rm, off, 16));
            const float mn   = fmaxf(mrow[i], rm);
            const float corr = __expf(mrow[i] - mn);
            float rs = 0.f;
#pragma unroll
            for (int j = 0; j < 4; j++) {
                s[i][j] = __expf(s[i][j] - mn);
                rs += s[i][j];
            }
#pragma unroll
            for (int off = 8; off > 0; off >>= 1)
                rs += __shfl_xor_sync(0xffffffffu, rs, off, 16);
            lrow[i] = lrow[i] * corr + rs;
            mrow[i] = mn;
#pragma unroll
            for (int j = 0; j < 4; j++) acc[i][j] *= corr;
        }

        __syncthreads();   // everyone done reading Kt as K-tile
        // Store P into Kt as [q][k] (float4, conflict-free)
#pragma unroll
        for (int i = 0; i < 4; i++) {
            float4 pv = make_float4(s[i][0], s[i][1], s[i][2], s[i][3]);
            *(float4*)(Kt + (ty * 4 + i) * AST + tx * 4) = pv;
        }
        __syncthreads();

        // O += P V  (k unrolled by 4)
#pragma unroll 4
        for (int k0 = 0; k0 < 64; k0 += 4) {
            float P[4][4], V[4][4];
#pragma unroll
            for (int i = 0; i < 4; i++) {
                float4 p4 = *(const float4*)(Kt + (ty * 4 + i) * AST + k0);
                P[i][0] = p4.x; P[i][1] = p4.y; P[i][2] = p4.z; P[i][3] = p4.w;
            }
#pragma unroll
            for (int u = 0; u < 4; u++) {
                float4 v4 = *(const float4*)(Vs + (k0 + u) * AST + tx * 4);
                V[u][0] = v4.x; V[u][1] = v4.y; V[u][2] = v4.z; V[u][3] = v4.w;
            }
#pragma unroll
            for (int i = 0; i < 4; i++)
#pragma unroll
                for (int j = 0; j < 4; j++) {
                    acc[i][j] = fmaf(P[i][0], V[0][j], acc[i][j]);
                    acc[i][j] = fmaf(P[i][1], V[1][j], acc[i][j]);
                    acc[i][j] = fmaf(P[i][2], V[2][j], acc[i][j]);
                    acc[i][j] = fmaf(P[i][3], V[3][j], acc[i][j]);
                }
        }
    }

    // Normalize and write to g_ao[b*SEQ+n][h*64+d]
#pragma unroll
    for (int i = 0; i < 4; i++) {
        const float inv = 1.0f / lrow[i];
        float4 o;
        o.x = acc[i][0] * inv; o.y = acc[i][1] * inv;
        o.z = acc[i][2] * inv; o.w = acc[i][3] * inv;
        const size_t row = (size_t)b * SEQ + qt * 64 + ty * 4 + i;
        *(float4*)&g_ao[row * HIDDEN + h * HDIM + tx * 4] = o;
    }
}

// ---------------------------------------------------------------------------
// Launch
// ---------------------------------------------------------------------------
extern "C" void kernel_launch(void* const* d_in, const int* in_sizes, int n_in,
                              void* d_out, int out_size)
{
    const float* x    = (const float*)d_in[0];
    const float* Wqkv = (const float*)d_in[1];
    const float* bqkv = (const float*)d_in[2];
    const float* Wo   = (const float*)d_in[3];
    const float* bo   = (const float*)d_in[4];
    float* out = (float*)d_out;

    cudaFuncSetAttribute(attn_kernel,
                         cudaFuncAttributeMaxDynamicSharedMemorySize, ATTN_SMEM);

    // QKV projection + head scatter
    dim3 gq(3 * HIDDEN / BN, MROWS / BM);
    sgemm_kernel<<<gq, 256>>>(x, Wqkv, bqkv, nullptr,
                              MROWS, 3 * HIDDEN, HIDDEN, 1);

    // Fused attention
    attn_kernel<<<dim3(SEQ / 64, NHEADS, BATCH), 256, ATTN_SMEM>>>();

    // Output projection (reads g_ao)
    dim3 go(HIDDEN / BN, MROWS / BM);
    sgemm_kernel<<<go, 256>>>(nullptr, Wo, bo, out,
                              MROWS, HIDDEN, HIDDEN, 0);
}

// round 4
// speedup vs baseline: 1.0013x; 1.0013x over previous
#include <cuda_runtime.h>

#define HIDDEN   1024
#define BATCH    2
#define SEQ      2048
#define NHEADS   16
#define HDIM     64
#define MROWS    (BATCH * SEQ)   // 4096

// ---------------------------------------------------------------------------
// Scratch (static device globals — no runtime allocation allowed)
// ---------------------------------------------------------------------------
__device__ __align__(256) float g_q[BATCH * NHEADS * SEQ * HDIM];   // 16 MB
__device__ __align__(256) float g_k[BATCH * NHEADS * SEQ * HDIM];   // 16 MB
__device__ __align__(256) float g_v[BATCH * NHEADS * SEQ * HDIM];   // 16 MB
__device__ __align__(256) float g_ao[MROWS * HIDDEN];               // 16 MB

// ---------------------------------------------------------------------------
// SGEMM: C[M,N] = A[M,K] @ B[N,K]^T + bias[N]
//   mode 0: plain write to C (used for O-projection; A==nullptr -> read g_ao)
//   mode 1: scatter epilogue into g_q/g_k/g_v head-major layout
// Tiling: BM=128, BN=128, BK=16, 256 threads, 8x8 microtile per thread.
// ---------------------------------------------------------------------------
#define BM  128
#define BN  128
#define BKK 16

__global__ __launch_bounds__(256, 2)
void sgemm_kernel(const float* __restrict__ A, const float* __restrict__ Bm,
                  const float* __restrict__ bias, float* __restrict__ C,
                  int M, int N, int K, int mode)
{
    __shared__ float As[BKK][BM + 4];
    __shared__ float Bs[BKK][BN + 4];

    const int tid = threadIdx.x;
    const int tx  = tid & 15;      // 0..15 -> N microtile
    const int ty  = tid >> 4;      // 0..15 -> M microtile
    const int bm  = blockIdx.y * BM;
    const int bn  = blockIdx.x * BN;

    const float* Aeff = A ? A : g_ao;

    // Loader mapping: each thread loads 2 float4 from A and 2 from B per k-step
    const int ar = tid >> 2;           // 0..63
    const int ac = (tid & 3) << 2;     // 0,4,8,12
    const float* ap = Aeff + (size_t)(bm + ar) * K + ac;
    const float* bp = Bm   + (size_t)(bn + ar) * K + ac;

    float acc[8][8];
#pragma unroll
    for (int i = 0; i < 8; i++)
#pragma unroll
        for (int j = 0; j < 8; j++) acc[i][j] = 0.f;

    for (int k0 = 0; k0 < K; k0 += BKK) {
        float4 a0 = *(const float4*)(ap);
        float4 a1 = *(const float4*)(ap + (size_t)64 * K);
        float4 b0 = *(const float4*)(bp);
        float4 b1 = *(const float4*)(bp + (size_t)64 * K);
        ap += BKK; bp += BKK;

        __syncthreads();   // previous compute phase done reading smem
        As[ac + 0][ar]      = a0.x; As[ac + 1][ar]      = a0.y;
        As[ac + 2][ar]      = a0.z; As[ac + 3][ar]      = a0.w;
        As[ac + 0][ar + 64] = a1.x; As[ac + 1][ar + 64] = a1.y;
        As[ac + 2][ar + 64] = a1.z; As[ac + 3][ar + 64] = a1.w;
        Bs[ac + 0][ar]      = b0.x; Bs[ac + 1][ar]      = b0.y;
        Bs[ac + 2][ar]      = b0.z; Bs[ac + 3][ar]      = b0.w;
        Bs[ac + 0][ar + 64] = b1.x; Bs[ac + 1][ar + 64] = b1.y;
        Bs[ac + 2][ar + 64] = b1.z; Bs[ac + 3][ar + 64] = b1.w;
        __syncthreads();

#pragma unroll
        for (int kk = 0; kk < BKK; kk++) {
            float ra[8], rb[8];
            *(float4*)&ra[0] = *(const float4*)&As[kk][ty * 8];
            *(float4*)&ra[4] = *(const float4*)&As[kk][ty * 8 + 4];
            *(float4*)&rb[0] = *(const float4*)&Bs[kk][tx * 8];
            *(float4*)&rb[4] = *(const float4*)&Bs[kk][tx * 8 + 4];
#pragma unroll
            for (int i = 0; i < 8; i++)
#pragma unroll
                for (int j = 0; j < 8; j++)
                    acc[i][j] = fmaf(ra[i], rb[j], acc[i][j]);
        }
    }

    float rbias[8];
#pragma unroll
    for (int j = 0; j < 8; j++) rbias[j] = bias[bn + tx * 8 + j];

    if (mode == 0) {
#pragma unroll
        for (int i = 0; i < 8; i++) {
            const int row = bm + ty * 8 + i;
            float4 v0, v1;
            v0.x = acc[i][0] + rbias[0]; v0.y = acc[i][1] + rbias[1];
            v0.z = acc[i][2] + rbias[2]; v0.w = acc[i][3] + rbias[3];
            v1.x = acc[i][4] + rbias[4]; v1.y = acc[i][5] + rbias[5];
            v1.z = acc[i][6] + rbias[6]; v1.w = acc[i][7] + rbias[7];
            *(float4*)&C[(size_t)row * N + bn + tx * 8]     = v0;
            *(float4*)&C[(size_t)row * N + bn + tx * 8 + 4] = v1;
        }
    } else {
        // Scatter into g_q/g_k/g_v as [b][h][n][hd]
#pragma unroll
        for (int i = 0; i < 8; i++) {
            const int m = bm + ty * 8 + i;
            const int b = m >> 11;          // /SEQ (2048)
            const int n = m & 2047;
#pragma unroll
            for (int jj = 0; jj < 8; jj += 4) {
                const int e    = bn + tx * 8 + jj;
                const int part = e >> 10;       // 0:q 1:k 2:v
                const int c    = e & 1023;
                const int h    = c >> 6;
                const int hd   = c & 63;        // hd .. hd+3 stay in same head
                float* dst = (part == 0) ? g_q : ((part == 1) ? g_k : g_v);
                float4 v;
                v.x = acc[i][jj + 0] + rbias[jj + 0];
                v.y = acc[i][jj + 1] + rbias[jj + 1];
                v.z = acc[i][jj + 2] + rbias[jj + 2];
                v.w = acc[i][jj + 3] + rbias[jj + 3];
                *(float4*)&dst[(((size_t)(b * NHEADS + h) * SEQ) + n) * HDIM + hd] = v;
            }
        }
    }
}

// ---------------------------------------------------------------------------
// Fused flash attention (fp32, online softmax).
// Block: 64 queries x full HDIM=64 of one (b,h). 256 threads, 4x4 microtiles.
// Smem (dynamic, 52224 B): Qt[d][q], Kt[d][k] (reused as P[q][k]), Vs[k][d],
// all stride 68 floats.
// ---------------------------------------------------------------------------
#define AST 68
#define ATTN_SMEM (3 * 64 * AST * 4)

__global__ __launch_bounds__(256)
void attn_kernel()
{
    extern __shared__ float sm[];
    float* Qt = sm;                 // [d][q]
    float* Kt = sm + 64 * AST;      // [d][k], then reused as P[q][k]
    float* Vs = sm + 2 * 64 * AST;  // [k][d]

    const int tid = threadIdx.x;
    const int tx  = tid & 15;       // key / d-column microtile
    const int ty  = tid >> 4;       // query microtile
    const int qt  = blockIdx.x;     // 0..31
    const int h   = blockIdx.y;
    const int b   = blockIdx.z;

    const size_t head_off = (size_t)(b * NHEADS + h) * SEQ * HDIM;
    const float* qp = g_q + head_off + (size_t)qt * 64 * HDIM;
    const float* kp = g_k + head_off;
    const float* vp = g_v + head_off;

    const int lr = tid >> 2;            // 0..63
    const int lc = (tid & 3) << 4;      // 0,16,32,48

    // Load Q tile transposed: Qt[d][q]
#pragma unroll
    for (int u = 0; u < 4; u++) {
        float4 v = *(const float4*)(qp + (size_t)lr * HDIM + lc + u * 4);
        Qt[(lc + u * 4 + 0) * AST + lr] = v.x;
        Qt[(lc + u * 4 + 1) * AST + lr] = v.y;
        Qt[(lc + u * 4 + 2) * AST + lr] = v.z;
        Qt[(lc + u * 4 + 3) * AST + lr] = v.w;
    }

    float acc[4][4];
    float mrow[4], lrow[4];
#pragma unroll
    for (int i = 0; i < 4; i++) {
        mrow[i] = -3.0e38f;
        lrow[i] = 0.f;
#pragma unroll
        for (int j = 0; j < 4; j++) acc[i][j] = 0.f;
    }

    for (int kt = 0; kt < SEQ / 64; kt++) {
        float4 kreg[4], vreg[4];
        const float* kr = kp + (size_t)kt * 64 * HDIM + (size_t)lr * HDIM + lc;
        const float* vr = vp + (size_t)kt * 64 * HDIM + (size_t)lr * HDIM + lc;
#pragma unroll
        for (int u = 0; u < 4; u++) {
            kreg[u] = *(const float4*)(kr + u * 4);
            vreg[u] = *(const float4*)(vr + u * 4);
        }

        __syncthreads();   // previous PV done with Kt/Vs (and Qt visible on iter 0)
#pragma unroll
        for (int u = 0; u < 4; u++) {
            Kt[(lc + u * 4 + 0) * AST + lr] = kreg[u].x;
            Kt[(lc + u * 4 + 1) * AST + lr] = kreg[u].y;
            Kt[(lc + u * 4 + 2) * AST + lr] = kreg[u].z;
            Kt[(lc + u * 4 + 3) * AST + lr] = kreg[u].w;
            *(float4*)(Vs + lr * AST + lc + u * 4) = vreg[u];
        }
        __syncthreads();

        // S = Q K^T (4x4 per thread)
        float s[4][4];
#pragma unroll
        for (int i = 0; i < 4; i++)
#pragma unroll
            for (int j = 0; j < 4; j++) s[i][j] = 0.f;

#pragma unroll 8
        for (int d = 0; d < HDIM; d++) {
            float4 q4 = *(const float4*)(Qt + d * AST + ty * 4);
            float4 k4 = *(const float4*)(Kt + d * AST + tx * 4);
            float qa[4] = {q4.x, q4.y, q4.z, q4.w};
            float ka[4] = {k4.x, k4.y, k4.z, k4.w};
#pragma unroll
            for (int i = 0; i < 4; i++)
#pragma unroll
                for (int j = 0; j < 4; j++)
                    s[i][j] = fmaf(qa[i], ka[j], s[i][j]);
        }

        // Online softmax update (rows owned by 16-lane groups sharing ty)
#pragma unroll
        for (int i = 0; i < 4; i++) {
#pragma unroll
            for (int j = 0; j < 4; j++) s[i][j] *= 0.125f;   // 1/sqrt(64)
            float rm = fmaxf(fmaxf(s[i][0], s[i][1]), fmaxf(s[i][2], s[i][3]));
#pragma unroll
            for (int off = 8; off > 0; off >>= 1)
                rm = fmaxf(rm, __shfl_xor_sync(0xffffffffu, rm, off, 16));
            const float mn   = fmaxf(mrow[i], rm);
            const float corr = __expf(mrow[i] - mn);
            float rs = 0.f;
#pragma unroll
            for (int j = 0; j < 4; j++) {
                s[i][j] = __expf(s[i][j] - mn);
                rs += s[i][j];
            }
#pragma unroll
            for (int off = 8; off > 0; off >>= 1)
                rs += __shfl_xor_sync(0xffffffffu, rs, off, 16);
            lrow[i] = lrow[i] * corr + rs;
            mrow[i] = mn;
#pragma unroll
            for (int j = 0; j < 4; j++) acc[i][j] *= corr;
        }

        __syncthreads();   // everyone done reading Kt as K-tile
        // Store P into Kt as [q][k] (float4, conflict-free)
#pragma unroll
        for (int i = 0; i < 4; i++) {
            float4 pv = make_float4(s[i][0], s[i][1], s[i][2], s[i][3]);
            *(float4*)(Kt + (ty * 4 + i) * AST + tx * 4) = pv;
        }
        __syncthreads();

        // O += P V  (k unrolled by 4)
#pragma unroll 4
        for (int k0 = 0; k0 < 64; k0 += 4) {
            float P[4][4], V[4][4];
#pragma unroll
            for (int i = 0; i < 4; i++) {
                float4 p4 = *(const float4*)(Kt + (ty * 4 + i) * AST + k0);
                P[i][0] = p4.x; P[i][1] = p4.y; P[i][2] = p4.z; P[i][3] = p4.w;
            }
#pragma unroll
            for (int u = 0; u < 4; u++) {
                float4 v4 = *(const float4*)(Vs + (k0 + u) * AST + tx * 4);
                V[u][0] = v4.x; V[u][1] = v4.y; V[u][2] = v4.z; V[u][3] = v4.w;
            }
#pragma unroll
            for (int i = 0; i < 4; i++)
#pragma unroll
                for (int j = 0; j < 4; j++) {
                    acc[i][j] = fmaf(P[i][0], V[0][j], acc[i][j]);
                    acc[i][j] = fmaf(P[i][1], V[1][j], acc[i][j]);
                    acc[i][j] = fmaf(P[i][2], V[2][j], acc[i][j]);
                    acc[i][j] = fmaf(P[i][3], V[3][j], acc[i][j]);
                }
        }
    }

    // Normalize and write to g_ao[b*SEQ+n][h*64+d]
#pragma unroll
    for (int i = 0; i < 4; i++) {
        const float inv = 1.0f / lrow[i];
        float4 o;
        o.x = acc[i][0] * inv; o.y = acc[i][1] * inv;
        o.z = acc[i][2] * inv; o.w = acc[i][3] * inv;
        const size_t row = (size_t)b * SEQ + qt * 64 + ty * 4 + i;
        *(float4*)&g_ao[row * HIDDEN + h * HDIM + tx * 4] = o;
    }
}

// ---------------------------------------------------------------------------
// Launch
// ---------------------------------------------------------------------------
extern "C" void kernel_launch(void* const* d_in, const int* in_sizes, int n_in,
                              void* d_out, int out_size)
{
    const float* x    = (const float*)d_in[0];
    const float* Wqkv = (const float*)d_in[1];
    const float* bqkv = (const float*)d_in[2];
    const float* Wo   = (const float*)d_in[3];
    const float* bo   = (const float*)d_in[4];
    float* out = (float*)d_out;

    cudaFuncSetAttribute(attn_kernel,
                         cudaFuncAttributeMaxDynamicSharedMemorySize, ATTN_SMEM);

    // QKV projection + head scatter
    dim3 gq(3 * HIDDEN / BN, MROWS / BM);
    sgemm_kernel<<<gq, 256>>>(x, Wqkv, bqkv, nullptr,
                              MROWS, 3 * HIDDEN, HIDDEN, 1);

    // Fused attention
    attn_kernel<<<dim3(SEQ / 64, NHEADS, BATCH), 256, ATTN_SMEM>>>();

    // Output projection (reads g_ao)
    dim3 go(HIDDEN / BN, MROWS / BM);
    sgemm_kernel<<<go, 256>>>(nullptr, Wo, bo, out,
                              MROWS, HIDDEN, HIDDEN, 0);
}